// round 15
// baseline (speedup 1.0000x reference)
#include <cuda_runtime.h>
#include <cuda_bf16.h>
#include <cstdint>

// ---------------------------------------------------------------------------
// DeepTransitionRNN: T=512, B=128, D=256, H=256, L=4
//
//  1) memset(out), memset(g_Hv, g_Ht)
//  2) xproj_kernel: XP[t][m][hc][b] = x[t,b,:] @ Wm[:,hc]  (5 x-side mats)
//  3) rnn_kernel: persistent, 256 CTAs = 4 groups (32 batch rows) x 64 CTAs
//     (4 H-columns each), 2 CTAs/SM (__launch_bounds__(256,2)).
//     R15 exchange: h values are PLAIN fp32 [col][row] (4B/elem) + ONE tag per
//     128B line (col). Producer warp: 32 relaxed stores -> __syncwarp ->
//     lane0 st.release tag. Consumer warp: 32 tag acquires (one 128B line!) ->
//     ballot -> __syncwarp -> coalesced fp32 loads. Halves L2 exchange
//     traffic vs the 8B {val,tag} scheme while staying exact fp32.
// ---------------------------------------------------------------------------

#define T_STEPS 512
#define BATCH   128
#define DDIM    256
#define HDIM    256
#define NLAYERS 4
#define NMAT    16
#define GROUPS  4
#define RPG     32          // batch rows per group (= one 128B line per col)
#define CPC     4           // H columns per CTA
#define CPG     64          // CTAs per group
#define XP_MS   (HDIM*BATCH)
#define GPBANK  (8*4*128)   // floats per partials bank
#define WSM_F   (NMAT*HDIM*CPC)   // 16384 floats = 64KB

typedef unsigned long long ull;

// ---- device scratch (static globals: allocation-free) ----------------------
__device__ __align__(16) float    g_XP[(size_t)T_STEPS * 5 * HDIM * BATCH];
__device__ __align__(128) float    g_Hv[2][GROUPS][HDIM * RPG];  // values
__device__ __align__(128) unsigned g_Ht[2][GROUPS][HDIM];        // line tags

// ---- activations (fp32, error ~1e-7) ---------------------------------------
__device__ __forceinline__ float sigmoidf_(float x) {
    x = fminf(fmaxf(x, -30.f), 30.f);
    return 1.f / (1.f + __expf(-x));
}
__device__ __forceinline__ float tanhf_(float x) {
    x = fminf(fmaxf(x, -15.f), 15.f);
    float e = __expf(2.f * x);
    return (e - 1.f) / (e + 1.f);
}

#define FMA2(acc, a, b) \
    asm("fma.rn.f32x2 %0,%1,%2,%0;" : "+l"(acc) : "l"(a), "l"(b))
#define PACK2(d, s) \
    asm("mov.b64 %0,{%1,%1};" : "=l"(d) : "f"(s))
#define UNPK(s, lo, hi) \
    asm("mov.b64 {%0,%1},%2;" : "=f"(lo), "=f"(hi) : "l"(s))

__device__ __forceinline__ unsigned ld_acq32(const unsigned* p) {
    unsigned v;
    asm volatile("ld.acquire.gpu.global.u32 %0,[%1];"
                 : "=r"(v) : "l"(p) : "memory");
    return v;
}
__device__ __forceinline__ void st_rel32(unsigned* p, unsigned v) {
    asm volatile("st.release.gpu.global.u32 [%0],%1;"
                 :: "l"(p), "r"(v) : "memory");
}
__device__ __forceinline__ void st_rlxf(float* p, float v) {
    asm volatile("st.relaxed.gpu.global.f32 [%0],%1;"
                 :: "l"(p), "f"(v) : "memory");
}

// ---------------------------------------------------------------------------
// Kernel 1: x-projection GEMM (validated R7-R14, unchanged).
// ---------------------------------------------------------------------------
__global__ void __launch_bounds__(256) xproj_kernel(
    const float* __restrict__ x,
    const float* __restrict__ Wr, const float* __restrict__ Wz,
    const float* __restrict__ Wl, const float* __restrict__ Cx,
    const float* __restrict__ Wt)
{
    __shared__ float AsmT[16 * 68];
    __shared__ float Bsm [16 * 68];
    __shared__ float Csm [64 * 68];

    const int tid   = threadIdx.x;
    const int bn    = blockIdx.x;
    const int bm    = blockIdx.y;
    const int t     = bm >> 1;
    const int brow0 = (bm & 1) * 64;
    const int n0    = bn * 64;
    const int mat   = n0 >> 8;
    const int hc0   = n0 & 255;
    const float* Wsrc = (mat == 0) ? Wr : (mat == 1) ? Wz :
                        (mat == 2) ? Wl : (mat == 3) ? Cx : Wt;

    const int ty = tid >> 4;
    const int tx = tid & 15;

    ull acc[4][2];
    #pragma unroll
    for (int i = 0; i < 4; ++i) { acc[i][0] = 0ull; acc[i][1] = 0ull; }

    const int a_m = tid >> 2;
    const int a_k = (tid & 3) * 4;
    const int b_k = tid >> 4;
    const int b_c = (tid & 15) * 4;

    const float* ag = x + ((size_t)(t * BATCH + brow0 + a_m)) * DDIM + a_k;
    const float* bg = Wsrc + (size_t)b_k * HDIM + hc0 + b_c;

    for (int k0 = 0; k0 < DDIM; k0 += 16) {
        float4 av = *(const float4*)(ag + k0);
        AsmT[(a_k + 0) * 68 + a_m] = av.x;
        AsmT[(a_k + 1) * 68 + a_m] = av.y;
        AsmT[(a_k + 2) * 68 + a_m] = av.z;
        AsmT[(a_k + 3) * 68 + a_m] = av.w;
        float4 bv = *(const float4*)(bg + (size_t)k0 * HDIM);
        *(float4*)&Bsm[b_k * 68 + b_c] = bv;
        __syncthreads();

        #pragma unroll
        for (int k = 0; k < 16; ++k) {
            float4 a4 = *(const float4*)&AsmT[k * 68 + ty * 4];
            ulonglong2 wv = *(const ulonglong2*)&Bsm[k * 68 + tx * 4];
            ull a2;
            #define XPROJ_STEP(i, comp)                                          \
                PACK2(a2, comp);                                                 \
                FMA2(acc[i][0], a2, wv.x);                                       \
                FMA2(acc[i][1], a2, wv.y);
            XPROJ_STEP(0, a4.x)
            XPROJ_STEP(1, a4.y)
            XPROJ_STEP(2, a4.z)
            XPROJ_STEP(3, a4.w)
            #undef XPROJ_STEP
        }
        __syncthreads();
    }

    #pragma unroll
    for (int i = 0; i < 4; ++i) {
        float c0, c1, c2, c3;
        UNPK(acc[i][0], c0, c1);
        UNPK(acc[i][1], c2, c3);
        Csm[(tx * 4 + 0) * 68 + ty * 4 + i] = c0;
        Csm[(tx * 4 + 1) * 68 + ty * 4 + i] = c1;
        Csm[(tx * 4 + 2) * 68 + ty * 4 + i] = c2;
        Csm[(tx * 4 + 3) * 68 + ty * 4 + i] = c3;
    }
    __syncthreads();

    const int nl = tid >> 2;
    const int mq = tid & 3;
    float* dst = g_XP + ((size_t)((t * 5 + mat) * HDIM + hc0 + nl)) * BATCH
                 + brow0 + mq * 16;
    #pragma unroll
    for (int q = 0; q < 4; ++q) {
        float4 v = *(const float4*)&Csm[nl * 68 + mq * 16 + q * 4];
        *(float4*)(dst + q * 4) = v;
    }
}

// ---------------------------------------------------------------------------
// Line-tagged GEMM: NM matrices x 4 cols x 32 rows over warp w's 32-k slice.
// Poll 32 line-tags (ONE 128B load per sweep), then stream plain fp32 h.
// ---------------------------------------------------------------------------
template <int NM>
__device__ __forceinline__ void gemm_warp(
    const float* __restrict__ hv,       // value buffer [k][row]
    const unsigned* __restrict__ ht,    // line tags [k]
    const float* __restrict__ wbase,    // Wsm + first-matrix offset (stride 1024)
    float* __restrict__ bank,           // partials: [w][mat][elem(128)]
    int w, int lane, unsigned tag)
{
    // ---- poll this warp's 32 line tags (lane i -> line w*32+i) -------------
    {
        const unsigned* tp = ht + w * 32 + lane;
        unsigned v;
        do {
            v = ld_acq32(tp);
        } while (__ballot_sync(0xffffffffu, (int)(v - tag) < 0));
        __syncwarp();   // order every lane's data loads after ALL acquires
    }

    // ---- load h once (coalesced: 32 lines, 128B each) -----------------------
    const float* hp = hv + (w << 10) + lane;   // k = w*32 + i, row = lane
    float h[32];
    #pragma unroll
    for (int i = 0; i < 32; ++i) h[i] = __ldcg(hp + i * 32);

    // ---- FMA ----------------------------------------------------------------
    ull acc[NM * 2];
    #pragma unroll
    for (int i = 0; i < NM * 2; ++i) acc[i] = 0ull;

    const float* wk = wbase + w * 128;         // (w*32)*CPC floats
    #pragma unroll
    for (int i = 0; i < 32; ++i) {
        ull hd; PACK2(hd, h[i]);
        #pragma unroll
        for (int m = 0; m < NM; ++m) {
            const ulonglong2 wv = *(const ulonglong2*)(wk + m * 1024 + i * 4);
            FMA2(acc[m*2+0], hd, wv.x);
            FMA2(acc[m*2+1], hd, wv.y);
        }
    }

    float* gp = bank + (w * 4) * 128 + lane;   // mat stride 128 elems
    #pragma unroll
    for (int m = 0; m < NM; ++m) {
        #pragma unroll
        for (int cp = 0; cp < 2; ++cp) {
            float lo, hi;
            UNPK(acc[m*2+cp], lo, hi);
            gp[m*128 + (2*cp)   * 32] = lo;
            gp[m*128 + (2*cp+1) * 32] = hi;
        }
    }
}

// publish one h value: relaxed value store, warp-sync, lane0 releases the tag
__device__ __forceinline__ void publish(float* hv, unsigned* ht, int colg,
                                        int r, float val, unsigned newtag) {
    st_rlxf(hv + colg * 32 + r, val);
    __syncwarp();
    if (r == 0) st_rel32(ht + colg, newtag);
}

// ---------------------------------------------------------------------------
// Kernel 2: the recurrence. 256 CTAs x 256 threads, 2 CTAs per SM.
// Dynamic smem: Wsm 16x256x4 (64KB) | Gp 2 banks x 4096 (32KB)
// ---------------------------------------------------------------------------
#define SMEM_FLOATS (WSM_F + 2*GPBANK)
#define SMEM_BYTES  (SMEM_FLOATS * 4)

__global__ void __launch_bounds__(256, 2) rnn_kernel(
    const float* __restrict__ Wr, const float* __restrict__ Wz,
    const float* __restrict__ Wl, const float* __restrict__ Ch,
    const float* __restrict__ Tr, const float* __restrict__ Tz,
    const float* __restrict__ Tn,
    const int*   __restrict__ lengths,
    float*       __restrict__ out)
{
    extern __shared__ float smem[];
    float* Wsm = smem;                 // 16384 floats
    float* Gp  = smem + WSM_F;         // 2 x 4096 floats

    const int tid  = threadIdx.x;
    const int cta  = blockIdx.x;
    const int g    = cta >> 6;         // group 0..3
    const int cb   = cta & 63;         // column block within group
    const int col0 = cb * CPC;

    // ---- load this CTA's 4-column slice of all 16 h-side matrices ----------
    for (int idx = tid; idx < WSM_F; idx += 256) {
        int m = idx >> 10;
        int k = (idx >> 2) & 255;
        int c = idx & 3;
        const float* src;
        if (m == 0)      src = Wr + (size_t)(DDIM + k) * HDIM;
        else if (m == 1) src = Wz + (size_t)(DDIM + k) * HDIM;
        else if (m == 2) src = Wl + (size_t)(DDIM + k) * HDIM;
        else if (m == 3) src = Ch + (size_t)k * HDIM;
        else {
            int mm = m - 4, layer = mm / 3, which = mm % 3;
            const float* base = (which == 0) ? Tr : (which == 1) ? Tz : Tn;
            src = base + (size_t)layer * HDIM * HDIM + (size_t)k * HDIM;
        }
        Wsm[idx] = src[col0 + c];
    }
    __syncthreads();

    const int r     = tid & 31;        // row (epilogue) / GEMM lane
    const int cl    = tid >> 5;        // warp id; epilogue col for tid<128
    const int b     = g * RPG + r;
    const int colg  = col0 + cl;       // valid for tid<128 (cl<4)
    const int mylen = lengths[b];
    const int Lg    = lengths[g * RPG];    // sorted descending -> group max

    const int w    = cl;               // GEMM warp id
    const int lane = r;
    const bool epi = (tid < 128);      // epilogue threads (warps 0-3)

    unsigned p = 0;                    // global phase counter (tag base)
    float*    hv0 = &g_Hv[0][g][0];    // memset to 0 each launch
    float*    hv1 = &g_Hv[1][g][0];
    unsigned* ht0 = &g_Ht[0][g][0];
    unsigned* ht1 = &g_Ht[1][g][0];

    float hown = 0.f;

    for (int t = 0; t < Lg; ++t) {
        const bool act = (t < mylen);
        const float hstep = hown;

        float xr = 0.f, xz = 0.f, xl = 0.f, xc = 0.f, xw = 0.f;
        if (epi) {
            const float* xp = g_XP + ((size_t)(t * 5) * HDIM + colg) * BATCH + b;
            xr = __ldcg(xp + 0 * XP_MS);
            xz = __ldcg(xp + 1 * XP_MS);
            xl = __ldcg(xp + 2 * XP_MS);
            xc = __ldcg(xp + 3 * XP_MS);
            xw = __ldcg(xp + 4 * XP_MS);
        }

        // ================= phase A: 4 GEMMs, warp = k-slice ==================
        {
            const float*    rhv = (p & 1) ? hv1 : hv0;
            const unsigned* rht = (p & 1) ? ht1 : ht0;
            float*          bank = Gp + (p & 1) * GPBANK;
            gemm_warp<4>(rhv, rht, Wsm, bank, w, lane, p);
            __syncthreads();
            if (epi) {
                float gr = 0.f, gz = 0.f, gl = 0.f, gch = 0.f;
                #pragma unroll
                for (int ww = 0; ww < 8; ++ww) {
                    const float* q = bank + ww * 512 + tid;
                    gr += q[0]; gz += q[128]; gl += q[256]; gch += q[384];
                }
                float rv = sigmoidf_(xr + gr);
                float zv = sigmoidf_(xz + gz);
                float lv = sigmoidf_(xl + gl);
                float nv = tanhf_(xc + rv * gch) + lv * xw;
                hown = (1.f - zv) * hown + zv * nv;
                publish((p & 1) ? hv0 : hv1, (p & 1) ? ht0 : ht1,
                        colg, r, hown, p + 1);
            }
        }
        ++p;

        // ================= 4 transition layers (Tr,Tz,Tn) ===================
        #pragma unroll 1
        for (int layer = 0; layer < NLAYERS; ++layer) {
            const float*    rhv = (p & 1) ? hv1 : hv0;
            const unsigned* rht = (p & 1) ? ht1 : ht0;
            float*          bank = Gp + (p & 1) * GPBANK;
            gemm_warp<3>(rhv, rht, Wsm + (4 + 3 * layer) * 1024,
                         bank, w, lane, p);
            __syncthreads();
            if (epi) {
                float grr = 0.f, gzz = 0.f, gnn = 0.f;
                #pragma unroll
                for (int ww = 0; ww < 8; ++ww) {
                    const float* q = bank + ww * 512 + tid;
                    grr += q[0]; gzz += q[128]; gnn += q[256];
                }
                float rr = sigmoidf_(grr);
                float zz = sigmoidf_(gzz);
                float nn = tanhf_(rr * gnn);
                float hnew = (1.f - zz) * nn + zz * hown;

                float outval = 0.f;
                bool  dostore = false;
                if (layer == NLAYERS - 1) {
                    hown = act ? hnew : hstep;
                    outval  = hnew;
                    dostore = act;
                } else {
                    hown = hnew;
                }
                publish((p & 1) ? hv0 : hv1, (p & 1) ? ht0 : ht1,
                        colg, r, hown, p + 1);
                if (dostore)   // off the critical path
                    out[((size_t)t * BATCH + b) * HDIM + colg] = outval;
            }
            ++p;
        }
    }
}

// ---------------------------------------------------------------------------
// kernel_launch: memsets -> x-projection GEMM -> persistent recurrence
// ---------------------------------------------------------------------------
extern "C" void kernel_launch(void* const* d_in, const int* in_sizes, int n_in,
                              void* d_out, int out_size)
{
    const float* x       = (const float*)d_in[0];
    const int*   lengths = (const int*)  d_in[1];
    const float* Wr      = (const float*)d_in[2];
    const float* Wz      = (const float*)d_in[3];
    const float* Wl      = (const float*)d_in[4];
    const float* Wt      = (const float*)d_in[5];
    const float* Cx      = (const float*)d_in[6];
    const float* Ch      = (const float*)d_in[7];
    const float* Tr      = (const float*)d_in[8];
    const float* Tz      = (const float*)d_in[9];
    const float* Tn      = (const float*)d_in[10];
    float* out = (float*)d_out;
    (void)in_sizes; (void)n_in;

    cudaMemsetAsync(out, 0, (size_t)out_size * sizeof(float));

    // h values start at 0.0 (initial state), tags at 0 (phase-0 readiness).
    void* ptr = nullptr;
    cudaGetSymbolAddress(&ptr, g_Hv);
    cudaMemsetAsync(ptr, 0, sizeof(float) * 2 * GROUPS * HDIM * RPG);
    cudaGetSymbolAddress(&ptr, g_Ht);
    cudaMemsetAsync(ptr, 0, sizeof(unsigned) * 2 * GROUPS * HDIM);

    dim3 ggrid(20, 1024);
    xproj_kernel<<<ggrid, 256>>>(x, Wr, Wz, Wl, Cx, Wt);

    cudaFuncSetAttribute(rnn_kernel,
                         cudaFuncAttributeMaxDynamicSharedMemorySize,
                         SMEM_BYTES);
    rnn_kernel<<<GROUPS * CPG, 256, SMEM_BYTES>>>(
        Wr, Wz, Wl, Ch, Tr, Tz, Tn, lengths, out);
}

// round 16
// speedup vs baseline: 1.5885x; 1.5885x over previous
#include <cuda_runtime.h>
#include <cuda_bf16.h>
#include <cstdint>

// ---------------------------------------------------------------------------
// DeepTransitionRNN: T=512, B=128, D=256, H=256, L=4
//
//  1) memset(out), memset(g_Hbuf: tags -> 0)
//  2) xproj_kernel: XP[t][m][hc][b] = x[t,b,:] @ Wm[:,hc]  (5 x-side mats)
//  3) rnn_kernel: persistent, 256 CTAs = 4 groups (32 batch rows) x 64 CTAs
//     (4 H-columns each), 2 CTAs/SM (__launch_bounds__(256,2)).
//     Exchange (R14, proven): 8B {f32 val, u32 tag} elements in a 2-deep
//     ping-pong ring; consumers poll the distributed data words themselves.
//     R16: epilogue spread across ALL 8 warps (16 lanes each) and groups 2-3
//     start ~half a phase late so co-resident SMT partners run anti-phased.
// ---------------------------------------------------------------------------

#define T_STEPS 512
#define BATCH   128
#define DDIM    256
#define HDIM    256
#define NLAYERS 4
#define NMAT    16
#define GROUPS  4
#define RPG     32          // batch rows per group
#define CPC     4           // H columns per CTA
#define CPG     64          // CTAs per group
#define XP_MS   (HDIM*BATCH)
#define GPBANK  (8*4*128)   // floats per partials bank (8 warps x 4 mats x 128)
#define WSM_F   (NMAT*HDIM*CPC)   // 16384 floats = 64KB

typedef unsigned long long ull;

// ---- device scratch (static globals: allocation-free) ----------------------
__device__ __align__(16) float g_XP[(size_t)T_STEPS * 5 * HDIM * BATCH];
__device__ __align__(16) ull   g_Hbuf[2][GROUPS][HDIM * RPG];  // {val, tag}

// ---- activations (fp32, error ~1e-7) ---------------------------------------
__device__ __forceinline__ float sigmoidf_(float x) {
    x = fminf(fmaxf(x, -30.f), 30.f);
    return 1.f / (1.f + __expf(-x));
}
__device__ __forceinline__ float tanhf_(float x) {
    x = fminf(fmaxf(x, -15.f), 15.f);
    float e = __expf(2.f * x);
    return (e - 1.f) / (e + 1.f);
}

#define FMA2(acc, a, b) \
    asm("fma.rn.f32x2 %0,%1,%2,%0;" : "+l"(acc) : "l"(a), "l"(b))
#define PACK2(d, s) \
    asm("mov.b64 %0,{%1,%1};" : "=l"(d) : "f"(s))
#define UNPK(s, lo, hi) \
    asm("mov.b64 {%0,%1},%2;" : "=f"(lo), "=f"(hi) : "l"(s))

__device__ __forceinline__ ull ld_rlx64(const ull* p) {
    ull v;
    asm volatile("ld.relaxed.gpu.global.b64 %0,[%1];"
                 : "=l"(v) : "l"(p) : "memory");
    return v;
}
__device__ __forceinline__ void st_rlx64(ull* p, ull v) {
    asm volatile("st.relaxed.gpu.global.b64 [%0],%1;"
                 :: "l"(p), "l"(v) : "memory");
}

// ---------------------------------------------------------------------------
// Kernel 1: x-projection GEMM (validated R7-R15, unchanged).
// ---------------------------------------------------------------------------
__global__ void __launch_bounds__(256) xproj_kernel(
    const float* __restrict__ x,
    const float* __restrict__ Wr, const float* __restrict__ Wz,
    const float* __restrict__ Wl, const float* __restrict__ Cx,
    const float* __restrict__ Wt)
{
    __shared__ float AsmT[16 * 68];
    __shared__ float Bsm [16 * 68];
    __shared__ float Csm [64 * 68];

    const int tid   = threadIdx.x;
    const int bn    = blockIdx.x;
    const int bm    = blockIdx.y;
    const int t     = bm >> 1;
    const int brow0 = (bm & 1) * 64;
    const int n0    = bn * 64;
    const int mat   = n0 >> 8;
    const int hc0   = n0 & 255;
    const float* Wsrc = (mat == 0) ? Wr : (mat == 1) ? Wz :
                        (mat == 2) ? Wl : (mat == 3) ? Cx : Wt;

    const int ty = tid >> 4;
    const int tx = tid & 15;

    ull acc[4][2];
    #pragma unroll
    for (int i = 0; i < 4; ++i) { acc[i][0] = 0ull; acc[i][1] = 0ull; }

    const int a_m = tid >> 2;
    const int a_k = (tid & 3) * 4;
    const int b_k = tid >> 4;
    const int b_c = (tid & 15) * 4;

    const float* ag = x + ((size_t)(t * BATCH + brow0 + a_m)) * DDIM + a_k;
    const float* bg = Wsrc + (size_t)b_k * HDIM + hc0 + b_c;

    for (int k0 = 0; k0 < DDIM; k0 += 16) {
        float4 av = *(const float4*)(ag + k0);
        AsmT[(a_k + 0) * 68 + a_m] = av.x;
        AsmT[(a_k + 1) * 68 + a_m] = av.y;
        AsmT[(a_k + 2) * 68 + a_m] = av.z;
        AsmT[(a_k + 3) * 68 + a_m] = av.w;
        float4 bv = *(const float4*)(bg + (size_t)k0 * HDIM);
        *(float4*)&Bsm[b_k * 68 + b_c] = bv;
        __syncthreads();

        #pragma unroll
        for (int k = 0; k < 16; ++k) {
            float4 a4 = *(const float4*)&AsmT[k * 68 + ty * 4];
            ulonglong2 wv = *(const ulonglong2*)&Bsm[k * 68 + tx * 4];
            ull a2;
            #define XPROJ_STEP(i, comp)                                          \
                PACK2(a2, comp);                                                 \
                FMA2(acc[i][0], a2, wv.x);                                       \
                FMA2(acc[i][1], a2, wv.y);
            XPROJ_STEP(0, a4.x)
            XPROJ_STEP(1, a4.y)
            XPROJ_STEP(2, a4.z)
            XPROJ_STEP(3, a4.w)
            #undef XPROJ_STEP
        }
        __syncthreads();
    }

    #pragma unroll
    for (int i = 0; i < 4; ++i) {
        float c0, c1, c2, c3;
        UNPK(acc[i][0], c0, c1);
        UNPK(acc[i][1], c2, c3);
        Csm[(tx * 4 + 0) * 68 + ty * 4 + i] = c0;
        Csm[(tx * 4 + 1) * 68 + ty * 4 + i] = c1;
        Csm[(tx * 4 + 2) * 68 + ty * 4 + i] = c2;
        Csm[(tx * 4 + 3) * 68 + ty * 4 + i] = c3;
    }
    __syncthreads();

    const int nl = tid >> 2;
    const int mq = tid & 3;
    float* dst = g_XP + ((size_t)((t * 5 + mat) * HDIM + hc0 + nl)) * BATCH
                 + brow0 + mq * 16;
    #pragma unroll
    for (int q = 0; q < 4; ++q) {
        float4 v = *(const float4*)&Csm[nl * 68 + mq * 16 + q * 4];
        *(float4*)(dst + q * 4) = v;
    }
}

// ---------------------------------------------------------------------------
// Tagged-stream GEMM: NM matrices x 4 cols x 32 rows over warp w's 32-k slice.
// h elements are {val, tag} pairs; warp polls its own chunk's tags, chunks of
// 8 k, double-buffered. (R14-proven.)
// ---------------------------------------------------------------------------
template <int NM>
__device__ __forceinline__ void gemm_warp(
    const ull*  __restrict__ hb,      // tagged h buffer (read side of ring)
    const float* __restrict__ wbase,  // Wsm + first-matrix offset (mat stride 1024)
    float* __restrict__ bank,         // partials bank: [w][mat][elem(128)]
    int w, int lane, unsigned tag)
{
    ull acc[NM * 2];
    #pragma unroll
    for (int i = 0; i < NM * 2; ++i) acc[i] = 0ull;

    const ull* hp = hb + (w << 10) + lane;     // k = w*32 + i, row = lane
    const float* wk = wbase + w * 128;         // (w*32)*CPC floats

    ull d0[8], d1[8];

    // chunk 0: poll until every lane's 8 tags match
    for (;;) {
        #pragma unroll
        for (int i = 0; i < 8; ++i) d0[i] = ld_rlx64(hp + i * 32);
        bool ok = true;
        #pragma unroll
        for (int i = 0; i < 8; ++i) ok &= ((unsigned)(d0[i] >> 32) == tag);
        if (__ballot_sync(0xffffffffu, ok) == 0xffffffffu) break;
    }

    #pragma unroll
    for (int c = 0; c < 4; ++c) {
        if (c < 3) {
            #pragma unroll
            for (int i = 0; i < 8; ++i)
                d1[i] = ld_rlx64(hp + ((c + 1) * 8 + i) * 32);
        }
        #pragma unroll
        for (int i = 0; i < 8; ++i) {
            float h = __uint_as_float((unsigned)d0[i]);
            ull hd; PACK2(hd, h);
            #pragma unroll
            for (int m = 0; m < NM; ++m) {
                const ulonglong2 wv =
                    *(const ulonglong2*)(wk + m * 1024 + (c * 8 + i) * 4);
                FMA2(acc[m*2+0], hd, wv.x);
                FMA2(acc[m*2+1], hd, wv.y);
            }
        }
        if (c < 3) {
            for (;;) {
                bool ok = true;
                #pragma unroll
                for (int i = 0; i < 8; ++i)
                    ok &= ((unsigned)(d1[i] >> 32) == tag);
                if (__ballot_sync(0xffffffffu, ok) == 0xffffffffu) break;
                #pragma unroll
                for (int i = 0; i < 8; ++i)
                    d1[i] = ld_rlx64(hp + ((c + 1) * 8 + i) * 32);
            }
            #pragma unroll
            for (int i = 0; i < 8; ++i) d0[i] = d1[i];
        }
    }

    float* gp = bank + (w * 4) * 128 + lane;   // mat stride 128 elems
    #pragma unroll
    for (int m = 0; m < NM; ++m) {
        #pragma unroll
        for (int cp = 0; cp < 2; ++cp) {
            float lo, hi;
            UNPK(acc[m*2+cp], lo, hi);
            gp[m*128 + (2*cp)   * 32] = lo;
            gp[m*128 + (2*cp+1) * 32] = hi;
        }
    }
}

// ---------------------------------------------------------------------------
// Kernel 2: the recurrence. 256 CTAs x 256 threads, 2 CTAs per SM.
// Dynamic smem: Wsm 16x256x4 (64KB) | Gp 2 banks x 8(w) x 4(mat) x 128 (32KB)
// Epilogue spread: warp w, lanes 0-15 own elements (col = w/2,
// row = (w&1)*16 + lane). Groups 2-3 start ~half a phase late (SMT anti-phase).
// ---------------------------------------------------------------------------
#define SMEM_FLOATS (WSM_F + 2*GPBANK)
#define SMEM_BYTES  (SMEM_FLOATS * 4)

__global__ void __launch_bounds__(256, 2) rnn_kernel(
    const float* __restrict__ Wr, const float* __restrict__ Wz,
    const float* __restrict__ Wl, const float* __restrict__ Ch,
    const float* __restrict__ Tr, const float* __restrict__ Tz,
    const float* __restrict__ Tn,
    const int*   __restrict__ lengths,
    float*       __restrict__ out)
{
    extern __shared__ float smem[];
    float* Wsm = smem;                 // 16384 floats
    float* Gp  = smem + WSM_F;         // 2 x 4096 floats

    const int tid  = threadIdx.x;
    const int cta  = blockIdx.x;
    const int g    = cta >> 6;         // group 0..3
    const int cb   = cta & 63;         // column block within group
    const int col0 = cb * CPC;

    // ---- load this CTA's 4-column slice of all 16 h-side matrices ----------
    for (int idx = tid; idx < WSM_F; idx += 256) {
        int m = idx >> 10;
        int k = (idx >> 2) & 255;
        int c = idx & 3;
        const float* src;
        if (m == 0)      src = Wr + (size_t)(DDIM + k) * HDIM;
        else if (m == 1) src = Wz + (size_t)(DDIM + k) * HDIM;
        else if (m == 2) src = Wl + (size_t)(DDIM + k) * HDIM;
        else if (m == 3) src = Ch + (size_t)k * HDIM;
        else {
            int mm = m - 4, layer = mm / 3, which = mm % 3;
            const float* base = (which == 0) ? Tr : (which == 1) ? Tz : Tn;
            src = base + (size_t)layer * HDIM * HDIM + (size_t)k * HDIM;
        }
        Wsm[idx] = src[col0 + c];
    }
    __syncthreads();

    // stagger: co-resident SMT pairs are ~(bid, bid+148) -> groups pair as
    // (0,2) and (1,3). Delay groups 2-3 by ~half a phase to anti-align.
    if (g >= 2) {
        long long s0 = clock64();
        while (clock64() - s0 < 2200) { }
    }

    const int lane = tid & 31;         // GEMM lane (= row in h buffer)
    const int w    = tid >> 5;         // GEMM warp id

    // epilogue ownership: warp w, lanes 0-15 own (col = w/2, row = (w&1)*16+lane)
    const bool epi  = (lane < 16);
    const int  ecl  = w >> 1;                       // local column 0..3
    const int  erow = ((w & 1) << 4) + lane;        // row 0..31 (epi only)
    const int  ecol = col0 + ecl;                   // global H column
    const int  eb   = g * RPG + (epi ? erow : 0);   // global batch index
    const int  eidx = (ecl << 5) + erow;            // elem index in bank
    const int  hidx = ecol * 32 + erow;             // h buffer element index
    const int  mylen = lengths[eb];
    const int  Lg    = lengths[g * RPG];   // sorted descending -> group max

    unsigned p = 0;                    // global phase counter (tag base)
    ull* buf0 = &g_Hbuf[0][g][0];      // tags memset to 0 each launch
    ull* buf1 = &g_Hbuf[1][g][0];

    float hown = 0.f;

    for (int t = 0; t < Lg; ++t) {
        const bool act = (t < mylen);
        const float hstep = hown;

        float xr = 0.f, xz = 0.f, xl = 0.f, xc = 0.f, xw = 0.f;
        if (epi) {
            const float* xp = g_XP + ((size_t)(t * 5) * HDIM + ecol) * BATCH + eb;
            xr = __ldcg(xp + 0 * XP_MS);
            xz = __ldcg(xp + 1 * XP_MS);
            xl = __ldcg(xp + 2 * XP_MS);
            xc = __ldcg(xp + 3 * XP_MS);
            xw = __ldcg(xp + 4 * XP_MS);
        }

        // ================= phase A: 4 GEMMs, warp = k-slice ==================
        {
            const ull* rbuf = (p & 1) ? buf1 : buf0;
            float*     bank = Gp + (p & 1) * GPBANK;
            gemm_warp<4>(rbuf, Wsm, bank, w, lane, p);
            __syncthreads();
            if (epi) {
                float gr = 0.f, gz = 0.f, gl = 0.f, gch = 0.f;
                #pragma unroll
                for (int ww = 0; ww < 8; ++ww) {
                    const float* q = bank + ww * 512 + eidx;
                    gr += q[0]; gz += q[128]; gl += q[256]; gch += q[384];
                }
                float rv = sigmoidf_(xr + gr);
                float zv = sigmoidf_(xz + gz);
                float lv = sigmoidf_(xl + gl);
                float nv = tanhf_(xc + rv * gch) + lv * xw;
                hown = (1.f - zv) * hown + zv * nv;
                ull pk;
                asm("mov.b64 %0,{%1,%2};" : "=l"(pk)
                    : "r"(__float_as_uint(hown)), "r"(p + 1));
                st_rlx64(((p & 1) ? buf0 : buf1) + hidx, pk);   // publish
            }
        }
        ++p;

        // ================= 4 transition layers (Tr,Tz,Tn) ===================
        #pragma unroll 1
        for (int layer = 0; layer < NLAYERS; ++layer) {
            const ull* rbuf = (p & 1) ? buf1 : buf0;
            float*     bank = Gp + (p & 1) * GPBANK;
            gemm_warp<3>(rbuf, Wsm + (4 + 3 * layer) * 1024, bank, w, lane, p);
            __syncthreads();
            if (epi) {
                float grr = 0.f, gzz = 0.f, gnn = 0.f;
                #pragma unroll
                for (int ww = 0; ww < 8; ++ww) {
                    const float* q = bank + ww * 512 + eidx;
                    grr += q[0]; gzz += q[128]; gnn += q[256];
                }
                float rr = sigmoidf_(grr);
                float zz = sigmoidf_(gzz);
                float nn = tanhf_(rr * gnn);
                float hnew = (1.f - zz) * nn + zz * hown;

                float outval = 0.f;
                bool  dostore = false;
                if (layer == NLAYERS - 1) {
                    hown = act ? hnew : hstep;
                    outval  = hnew;
                    dostore = act;
                } else {
                    hown = hnew;
                }
                ull pk;
                asm("mov.b64 %0,{%1,%2};" : "=l"(pk)
                    : "r"(__float_as_uint(hown)), "r"(p + 1));
                st_rlx64(((p & 1) ? buf0 : buf1) + hidx, pk);   // publish first
                if (dostore)   // off the critical path
                    out[((size_t)t * BATCH + eb) * HDIM + ecol] = outval;
            }
            ++p;
        }
    }
}

// ---------------------------------------------------------------------------
// kernel_launch: memsets -> x-projection GEMM -> persistent recurrence
// ---------------------------------------------------------------------------
extern "C" void kernel_launch(void* const* d_in, const int* in_sizes, int n_in,
                              void* d_out, int out_size)
{
    const float* x       = (const float*)d_in[0];
    const int*   lengths = (const int*)  d_in[1];
    const float* Wr      = (const float*)d_in[2];
    const float* Wz      = (const float*)d_in[3];
    const float* Wl      = (const float*)d_in[4];
    const float* Wt      = (const float*)d_in[5];
    const float* Cx      = (const float*)d_in[6];
    const float* Ch      = (const float*)d_in[7];
    const float* Tr      = (const float*)d_in[8];
    const float* Tz      = (const float*)d_in[9];
    const float* Tn      = (const float*)d_in[10];
    float* out = (float*)d_out;
    (void)in_sizes; (void)n_in;

    cudaMemsetAsync(out, 0, (size_t)out_size * sizeof(float));

    // Ring buffer must start with {0.0f, tag=0} every launch. Graph-replay safe.
    void* hb_ptr = nullptr;
    cudaGetSymbolAddress(&hb_ptr, g_Hbuf);
    cudaMemsetAsync(hb_ptr, 0, sizeof(ull) * 2 * GROUPS * HDIM * RPG);

    dim3 ggrid(20, 1024);
    xproj_kernel<<<ggrid, 256>>>(x, Wr, Wz, Wl, Cx, Wt);

    cudaFuncSetAttribute(rnn_kernel,
                         cudaFuncAttributeMaxDynamicSharedMemorySize,
                         SMEM_BYTES);
    rnn_kernel<<<GROUPS * CPG, 256, SMEM_BYTES>>>(
        Wr, Wz, Wl, Ch, Tr, Tz, Tn, lengths, out);
}

// round 17
// speedup vs baseline: 1.7222x; 1.0842x over previous
#include <cuda_runtime.h>
#include <cuda_bf16.h>
#include <cstdint>

// ---------------------------------------------------------------------------
// DeepTransitionRNN: T=512, B=128, D=256, H=256, L=4
//
//  1) memset(out), memset(g_Hbuf)
//  2) xproj_kernel: XP[t][m][hc][b] = x[t,b,:] @ Wm[:,hc]  (5 x-side mats)
//  3) rnn_kernel: persistent, 256 CTAs = 4 groups (32 batch rows) x 64 CTAs
//     (4 H-columns each), 2 CTAs/SM (__launch_bounds__(256,2)).
//     R17 exchange: each h element is ONE 4-byte word whose low 4 mantissa
//     bits carry (phase & 15). Consumers poll the distributed data words
//     (proven scheme) at HALF the bytes of the 8B {val,tag} ring. The 2-deep
//     ring only ever exposes tags {q-2, q, q+2} to a consumer expecting q,
//     and +-2 != 0 mod 16, so the 4-bit tag disambiguates exactly. The
//     <=1.8e-6 relative mantissa perturbation is far inside the 1e-3 bound.
// ---------------------------------------------------------------------------

#define T_STEPS 512
#define BATCH   128
#define DDIM    256
#define HDIM    256
#define NLAYERS 4
#define NMAT    16
#define GROUPS  4
#define RPG     32          // batch rows per group
#define CPC     4           // H columns per CTA
#define CPG     64          // CTAs per group
#define XP_MS   (HDIM*BATCH)
#define GPBANK  (8*4*128)   // floats per partials bank (8 warps x 4 mats x 128)
#define WSM_F   (NMAT*HDIM*CPC)   // 16384 floats = 64KB

#define TAGMASK 15u
#define VALMASK 0xFFFFFFF0u

typedef unsigned long long ull;

// ---- device scratch (static globals: allocation-free) ----------------------
__device__ __align__(16) float    g_XP[(size_t)T_STEPS * 5 * HDIM * BATCH];
__device__ __align__(128) unsigned g_Hbuf[2][GROUPS][HDIM * RPG]; // tagged fp32

// ---- activations (fp32, error ~1e-7) ---------------------------------------
__device__ __forceinline__ float sigmoidf_(float x) {
    x = fminf(fmaxf(x, -30.f), 30.f);
    return 1.f / (1.f + __expf(-x));
}
__device__ __forceinline__ float tanhf_(float x) {
    x = fminf(fmaxf(x, -15.f), 15.f);
    float e = __expf(2.f * x);
    return (e - 1.f) / (e + 1.f);
}

#define FMA2(acc, a, b) \
    asm("fma.rn.f32x2 %0,%1,%2,%0;" : "+l"(acc) : "l"(a), "l"(b))
#define PACK2(d, s) \
    asm("mov.b64 %0,{%1,%1};" : "=l"(d) : "f"(s))
#define UNPK(s, lo, hi) \
    asm("mov.b64 {%0,%1},%2;" : "=f"(lo), "=f"(hi) : "l"(s))

__device__ __forceinline__ unsigned ld_rlx32(const unsigned* p) {
    unsigned v;
    asm volatile("ld.relaxed.gpu.global.u32 %0,[%1];"
                 : "=r"(v) : "l"(p) : "memory");
    return v;
}
__device__ __forceinline__ void st_rlx32(unsigned* p, unsigned v) {
    asm volatile("st.relaxed.gpu.global.u32 [%0],%1;"
                 :: "l"(p), "r"(v) : "memory");
}

// ---------------------------------------------------------------------------
// Kernel 1: x-projection GEMM (validated R7-R16, unchanged).
// ---------------------------------------------------------------------------
__global__ void __launch_bounds__(256) xproj_kernel(
    const float* __restrict__ x,
    const float* __restrict__ Wr, const float* __restrict__ Wz,
    const float* __restrict__ Wl, const float* __restrict__ Cx,
    const float* __restrict__ Wt)
{
    __shared__ float AsmT[16 * 68];
    __shared__ float Bsm [16 * 68];
    __shared__ float Csm [64 * 68];

    const int tid   = threadIdx.x;
    const int bn    = blockIdx.x;
    const int bm    = blockIdx.y;
    const int t     = bm >> 1;
    const int brow0 = (bm & 1) * 64;
    const int n0    = bn * 64;
    const int mat   = n0 >> 8;
    const int hc0   = n0 & 255;
    const float* Wsrc = (mat == 0) ? Wr : (mat == 1) ? Wz :
                        (mat == 2) ? Wl : (mat == 3) ? Cx : Wt;

    const int ty = tid >> 4;
    const int tx = tid & 15;

    ull acc[4][2];
    #pragma unroll
    for (int i = 0; i < 4; ++i) { acc[i][0] = 0ull; acc[i][1] = 0ull; }

    const int a_m = tid >> 2;
    const int a_k = (tid & 3) * 4;
    const int b_k = tid >> 4;
    const int b_c = (tid & 15) * 4;

    const float* ag = x + ((size_t)(t * BATCH + brow0 + a_m)) * DDIM + a_k;
    const float* bg = Wsrc + (size_t)b_k * HDIM + hc0 + b_c;

    for (int k0 = 0; k0 < DDIM; k0 += 16) {
        float4 av = *(const float4*)(ag + k0);
        AsmT[(a_k + 0) * 68 + a_m] = av.x;
        AsmT[(a_k + 1) * 68 + a_m] = av.y;
        AsmT[(a_k + 2) * 68 + a_m] = av.z;
        AsmT[(a_k + 3) * 68 + a_m] = av.w;
        float4 bv = *(const float4*)(bg + (size_t)k0 * HDIM);
        *(float4*)&Bsm[b_k * 68 + b_c] = bv;
        __syncthreads();

        #pragma unroll
        for (int k = 0; k < 16; ++k) {
            float4 a4 = *(const float4*)&AsmT[k * 68 + ty * 4];
            ulonglong2 wv = *(const ulonglong2*)&Bsm[k * 68 + tx * 4];
            ull a2;
            #define XPROJ_STEP(i, comp)                                          \
                PACK2(a2, comp);                                                 \
                FMA2(acc[i][0], a2, wv.x);                                       \
                FMA2(acc[i][1], a2, wv.y);
            XPROJ_STEP(0, a4.x)
            XPROJ_STEP(1, a4.y)
            XPROJ_STEP(2, a4.z)
            XPROJ_STEP(3, a4.w)
            #undef XPROJ_STEP
        }
        __syncthreads();
    }

    #pragma unroll
    for (int i = 0; i < 4; ++i) {
        float c0, c1, c2, c3;
        UNPK(acc[i][0], c0, c1);
        UNPK(acc[i][1], c2, c3);
        Csm[(tx * 4 + 0) * 68 + ty * 4 + i] = c0;
        Csm[(tx * 4 + 1) * 68 + ty * 4 + i] = c1;
        Csm[(tx * 4 + 2) * 68 + ty * 4 + i] = c2;
        Csm[(tx * 4 + 3) * 68 + ty * 4 + i] = c3;
    }
    __syncthreads();

    const int nl = tid >> 2;
    const int mq = tid & 3;
    float* dst = g_XP + ((size_t)((t * 5 + mat) * HDIM + hc0 + nl)) * BATCH
                 + brow0 + mq * 16;
    #pragma unroll
    for (int q = 0; q < 4; ++q) {
        float4 v = *(const float4*)&Csm[nl * 68 + mq * 16 + q * 4];
        *(float4*)(dst + q * 4) = v;
    }
}

// ---------------------------------------------------------------------------
// Tagged-stream GEMM: NM matrices x 4 cols x 32 rows over warp w's 32-k slice.
// h elements are 4B fp32 words with (phase & 15) in the low mantissa nibble;
// the warp polls its own chunk's nibbles, chunks of 8 k, double-buffered.
// ---------------------------------------------------------------------------
template <int NM>
__device__ __forceinline__ void gemm_warp(
    const unsigned* __restrict__ hb,  // tagged h buffer (read side of ring)
    const float* __restrict__ wbase,  // Wsm + first-matrix offset (mat stride 1024)
    float* __restrict__ bank,         // partials bank: [w][mat][elem(128)]
    int w, int lane, unsigned tag)
{
    ull acc[NM * 2];
    #pragma unroll
    for (int i = 0; i < NM * 2; ++i) acc[i] = 0ull;

    const unsigned* hp = hb + (w << 10) + lane;  // k = w*32 + i, row = lane
    const float* wk = wbase + w * 128;           // (w*32)*CPC floats
    const unsigned t4 = tag & TAGMASK;

    unsigned d0[8], d1[8];

    // chunk 0: poll until every lane's 8 tag-nibbles match
    for (;;) {
        #pragma unroll
        for (int i = 0; i < 8; ++i) d0[i] = ld_rlx32(hp + i * 32);
        bool ok = true;
        #pragma unroll
        for (int i = 0; i < 8; ++i) ok &= ((d0[i] & TAGMASK) == t4);
        if (__ballot_sync(0xffffffffu, ok) == 0xffffffffu) break;
    }

    #pragma unroll
    for (int c = 0; c < 4; ++c) {
        if (c < 3) {
            #pragma unroll
            for (int i = 0; i < 8; ++i)
                d1[i] = ld_rlx32(hp + ((c + 1) * 8 + i) * 32);
        }
        #pragma unroll
        for (int i = 0; i < 8; ++i) {
            float h = __uint_as_float(d0[i]);   // nibble noise <= 1.8e-6 rel
            ull hd; PACK2(hd, h);
            #pragma unroll
            for (int m = 0; m < NM; ++m) {
                const ulonglong2 wv =
                    *(const ulonglong2*)(wk + m * 1024 + (c * 8 + i) * 4);
                FMA2(acc[m*2+0], hd, wv.x);
                FMA2(acc[m*2+1], hd, wv.y);
            }
        }
        if (c < 3) {
            for (;;) {
                bool ok = true;
                #pragma unroll
                for (int i = 0; i < 8; ++i)
                    ok &= ((d1[i] & TAGMASK) == t4);
                if (__ballot_sync(0xffffffffu, ok) == 0xffffffffu) break;
                #pragma unroll
                for (int i = 0; i < 8; ++i)
                    d1[i] = ld_rlx32(hp + ((c + 1) * 8 + i) * 32);
            }
            #pragma unroll
            for (int i = 0; i < 8; ++i) d0[i] = d1[i];
        }
    }

    float* gp = bank + (w * 4) * 128 + lane;   // mat stride 128 elems
    #pragma unroll
    for (int m = 0; m < NM; ++m) {
        #pragma unroll
        for (int cp = 0; cp < 2; ++cp) {
            float lo, hi;
            UNPK(acc[m*2+cp], lo, hi);
            gp[m*128 + (2*cp)   * 32] = lo;
            gp[m*128 + (2*cp+1) * 32] = hi;
        }
    }
}

// ---------------------------------------------------------------------------
// Kernel 2: the recurrence. 256 CTAs x 256 threads, 2 CTAs per SM.
// Dynamic smem: Wsm 16x256x4 (64KB) | Gp 2 banks x 8(w) x 4(mat) x 128 (32KB)
// ---------------------------------------------------------------------------
#define SMEM_FLOATS (WSM_F + 2*GPBANK)
#define SMEM_BYTES  (SMEM_FLOATS * 4)

__global__ void __launch_bounds__(256, 2) rnn_kernel(
    const float* __restrict__ Wr, const float* __restrict__ Wz,
    const float* __restrict__ Wl, const float* __restrict__ Ch,
    const float* __restrict__ Tr, const float* __restrict__ Tz,
    const float* __restrict__ Tn,
    const int*   __restrict__ lengths,
    float*       __restrict__ out)
{
    extern __shared__ float smem[];
    float* Wsm = smem;                 // 16384 floats
    float* Gp  = smem + WSM_F;         // 2 x 4096 floats

    const int tid  = threadIdx.x;
    const int cta  = blockIdx.x;
    const int g    = cta >> 6;         // group 0..3
    const int cb   = cta & 63;         // column block within group
    const int col0 = cb * CPC;

    // ---- load this CTA's 4-column slice of all 16 h-side matrices ----------
    for (int idx = tid; idx < WSM_F; idx += 256) {
        int m = idx >> 10;
        int k = (idx >> 2) & 255;
        int c = idx & 3;
        const float* src;
        if (m == 0)      src = Wr + (size_t)(DDIM + k) * HDIM;
        else if (m == 1) src = Wz + (size_t)(DDIM + k) * HDIM;
        else if (m == 2) src = Wl + (size_t)(DDIM + k) * HDIM;
        else if (m == 3) src = Ch + (size_t)k * HDIM;
        else {
            int mm = m - 4, layer = mm / 3, which = mm % 3;
            const float* base = (which == 0) ? Tr : (which == 1) ? Tz : Tn;
            src = base + (size_t)layer * HDIM * HDIM + (size_t)k * HDIM;
        }
        Wsm[idx] = src[col0 + c];
    }
    __syncthreads();

    const int r     = tid & 31;        // row (epilogue) / GEMM lane
    const int cl    = tid >> 5;        // warp id; epilogue col for tid<128
    const int b     = g * RPG + r;
    const int colg  = col0 + cl;       // valid for tid<128 (cl<4)
    const int mylen = lengths[b];
    const int Lg    = lengths[g * RPG];    // sorted descending -> group max

    const int w    = cl;               // GEMM warp id
    const int lane = r;
    const bool epi = (tid < 128);      // epilogue threads (warps 0-3)

    unsigned p = 0;                    // global phase counter (tag base)
    unsigned* buf0 = &g_Hbuf[0][g][0]; // memset to 0 each launch
    unsigned* buf1 = &g_Hbuf[1][g][0];

    const int hidx = colg * 32 + r;    // epilogue threads only
    float hown = 0.f;

    for (int t = 0; t < Lg; ++t) {
        const bool act = (t < mylen);
        const float hstep = hown;

        float xr = 0.f, xz = 0.f, xl = 0.f, xc = 0.f, xw = 0.f;
        if (epi) {
            const float* xp = g_XP + ((size_t)(t * 5) * HDIM + colg) * BATCH + b;
            xr = __ldcg(xp + 0 * XP_MS);
            xz = __ldcg(xp + 1 * XP_MS);
            xl = __ldcg(xp + 2 * XP_MS);
            xc = __ldcg(xp + 3 * XP_MS);
            xw = __ldcg(xp + 4 * XP_MS);
        }

        // ================= phase A: 4 GEMMs, warp = k-slice ==================
        {
            const unsigned* rbuf = (p & 1) ? buf1 : buf0;
            float*          bank = Gp + (p & 1) * GPBANK;
            gemm_warp<4>(rbuf, Wsm, bank, w, lane, p);
            __syncthreads();
            if (epi) {
                float gr = 0.f, gz = 0.f, gl = 0.f, gch = 0.f;
                #pragma unroll
                for (int ww = 0; ww < 8; ++ww) {
                    const float* q = bank + ww * 512 + tid;
                    gr += q[0]; gz += q[128]; gl += q[256]; gch += q[384];
                }
                float rv = sigmoidf_(xr + gr);
                float zv = sigmoidf_(xz + gz);
                float lv = sigmoidf_(xl + gl);
                float nv = tanhf_(xc + rv * gch) + lv * xw;
                hown = (1.f - zv) * hown + zv * nv;
                unsigned pk = (__float_as_uint(hown) & VALMASK)
                              | ((p + 1) & TAGMASK);
                st_rlx32(((p & 1) ? buf0 : buf1) + hidx, pk);   // publish
            }
        }
        ++p;

        // ================= 4 transition layers (Tr,Tz,Tn) ===================
        #pragma unroll 1
        for (int layer = 0; layer < NLAYERS; ++layer) {
            const unsigned* rbuf = (p & 1) ? buf1 : buf0;
            float*          bank = Gp + (p & 1) * GPBANK;
            gemm_warp<3>(rbuf, Wsm + (4 + 3 * layer) * 1024, bank, w, lane, p);
            __syncthreads();
            if (epi) {
                float grr = 0.f, gzz = 0.f, gnn = 0.f;
                #pragma unroll
                for (int ww = 0; ww < 8; ++ww) {
                    const float* q = bank + ww * 512 + tid;
                    grr += q[0]; gzz += q[128]; gnn += q[256];
                }
                float rr = sigmoidf_(grr);
                float zz = sigmoidf_(gzz);
                float nn = tanhf_(rr * gnn);
                float hnew = (1.f - zz) * nn + zz * hown;

                float outval = 0.f;
                bool  dostore = false;
                if (layer == NLAYERS - 1) {
                    hown = act ? hnew : hstep;
                    outval  = hnew;
                    dostore = act;
                } else {
                    hown = hnew;
                }
                unsigned pk = (__float_as_uint(hown) & VALMASK)
                              | ((p + 1) & TAGMASK);
                st_rlx32(((p & 1) ? buf0 : buf1) + hidx, pk);   // publish first
                if (dostore)   // off the critical path
                    out[((size_t)t * BATCH + b) * HDIM + colg] = outval;
            }
            ++p;
        }
    }
}

// ---------------------------------------------------------------------------
// kernel_launch: memsets -> x-projection GEMM -> persistent recurrence
// ---------------------------------------------------------------------------
extern "C" void kernel_launch(void* const* d_in, const int* in_sizes, int n_in,
                              void* d_out, int out_size)
{
    const float* x       = (const float*)d_in[0];
    const int*   lengths = (const int*)  d_in[1];
    const float* Wr      = (const float*)d_in[2];
    const float* Wz      = (const float*)d_in[3];
    const float* Wl      = (const float*)d_in[4];
    const float* Wt      = (const float*)d_in[5];
    const float* Cx      = (const float*)d_in[6];
    const float* Ch      = (const float*)d_in[7];
    const float* Tr      = (const float*)d_in[8];
    const float* Tz      = (const float*)d_in[9];
    const float* Tn      = (const float*)d_in[10];
    float* out = (float*)d_out;
    (void)in_sizes; (void)n_in;

    cudaMemsetAsync(out, 0, (size_t)out_size * sizeof(float));

    // Ring starts as 0.0f with tag-nibble 0 == phase-0 readiness. Replay-safe.
    void* hb_ptr = nullptr;
    cudaGetSymbolAddress(&hb_ptr, g_Hbuf);
    cudaMemsetAsync(hb_ptr, 0, sizeof(unsigned) * 2 * GROUPS * HDIM * RPG);

    dim3 ggrid(20, 1024);
    xproj_kernel<<<ggrid, 256>>>(x, Wr, Wz, Wl, Cx, Wt);

    cudaFuncSetAttribute(rnn_kernel,
                         cudaFuncAttributeMaxDynamicSharedMemorySize,
                         SMEM_BYTES);
    rnn_kernel<<<GROUPS * CPG, 256, SMEM_BYTES>>>(
        Wr, Wz, Wl, Ch, Tr, Tz, Tn, lengths, out);
}